// round 16
// baseline (speedup 1.0000x reference)
#include <cuda_runtime.h>
#include <cuda_bf16.h>

#define PADDING_IDX 0
#define SMOOTHING   0.1f
#define MAX_ROWS    8192

// Generation-tagged partial slots: {f32 value, u32 gen} in one aligned 8B word.
// One 8B store publishes value+tag atomically -> no fences/atomics anywhere.
// __device__ globals: allocation-free per harness rules.
__device__ unsigned long long g_slot[MAX_ROWS];   // zero-init: gen=0
__device__ unsigned int       g_gen = 0;          // bumped by spinner each launch

__device__ __forceinline__ void slot_store(int r, float v, unsigned int gen) {
    unsigned long long w =
        ((unsigned long long)gen << 32) | (unsigned long long)__float_as_uint(v);
    asm volatile("st.global.volatile.u64 [%0], %1;"
                 :: "l"(&g_slot[r]), "l"(w) : "memory");
}
__device__ __forceinline__ unsigned long long slot_load(int r) {
    unsigned long long w;
    asm volatile("ld.global.volatile.u64 %0, [%1];"
                 : "=l"(w) : "l"(&g_slot[r]) : "memory");
    return w;
}

// grid = N+1. Identical to the confirmed-best R10/R15 kernel EXCEPT the
// streaming loads use __ldcs (evict-first): 524MB single-pass through a
// 126MB L2 shouldn't thrash evict-normal lines. Single-variable test.
// NOTE: target is int32 on device (JAX x64-disabled downcasts int64 -> int32).
__global__ void __launch_bounds__(256)
ls_kernel(const float* __restrict__ x,
          const int* __restrict__ target,
          float* __restrict__ out,
          int V, int N)
{
    __shared__ float sh[8];
    const unsigned int gen = g_gen + 1u;   // L2-hot broadcast; stable during launch

    if (blockIdx.x != 0) {
        // ---------------- worker: stream one row ----------------
        const int r = blockIdx.x - 1;
        const int t = target[r];

        if (t == PADDING_IDX || t < 0 || t >= V) {
            if (threadIdx.x == 0) slot_store(r, 0.0f, gen);
            return;
        }

        const size_t row_off = (size_t)r * (size_t)V;
        const float4* __restrict__ row4 = reinterpret_cast<const float4*>(x + row_off);
        const int nv4 = V >> 2;                      // 32000 -> 8000 float4

        float s = 0.0f;
        for (int i = threadIdx.x; i < nv4; i += blockDim.x) {
            float4 v = __ldcs(&row4[i]);             // evict-first streaming load
            s += (v.x + v.y) + (v.z + v.w);
        }
        for (int i = (nv4 << 2) + threadIdx.x; i < V; i += blockDim.x)
            s += __ldcs(&x[row_off + i]);            // tail (unused for V=32000)

        #pragma unroll
        for (int o = 16; o > 0; o >>= 1)
            s += __shfl_down_sync(0xffffffffu, s, o);
        if ((threadIdx.x & 31) == 0) sh[threadIdx.x >> 5] = s;
        __syncthreads();

        if (threadIdx.x < 32) {
            float v = (threadIdx.x < 8) ? sh[threadIdx.x] : 0.0f;
            #pragma unroll
            for (int o = 4; o > 0; o >>= 1)
                v += __shfl_down_sync(0xffffffffu, v, o);
            if (threadIdx.x == 0) {
                const float g = x[row_off + (size_t)t];   // gather: default policy
                slot_store(r, -(SMOOTHING / (float)V) * v - (1.0f - SMOOTHING) * g, gen);
            }
        }
        return;
    }

    // ------------- spinner (block 0): consume-as-ready sweep -------------
    // Thread t owns slots {t, t+256, ..., t+3840}; fixed slot order per
    // thread -> deterministic accumulation.
    const int nslots = (N + 255) >> 8;               // 16 for N=4096
    float acc[16];
    #pragma unroll
    for (int k = 0; k < 16; k++) acc[k] = 0.0f;

    unsigned int pend = (nslots >= 32) ? 0xFFFFFFFFu : ((1u << nslots) - 1u);
    #pragma unroll
    for (int k = 0; k < 16; k++)
        if ((int)threadIdx.x + (k << 8) >= N) pend &= ~(1u << k);

    while (pend) {
        unsigned int made = 0;
        #pragma unroll
        for (int k = 0; k < 16; k++) {
            if (pend & (1u << k)) {
                unsigned long long w = slot_load(threadIdx.x + (k << 8));
                if ((unsigned int)(w >> 32) == gen) {
                    acc[k] = __uint_as_float((unsigned int)w);
                    pend &= ~(1u << k);
                    made = 1;
                }
            }
        }
        if (!made) __nanosleep(128);                 // back off only if stalled
    }

    float s = 0.0f;
    #pragma unroll
    for (int k = 0; k < 16; k++) s += acc[k];

    #pragma unroll
    for (int o = 16; o > 0; o >>= 1)
        s += __shfl_down_sync(0xffffffffu, s, o);
    if ((threadIdx.x & 31) == 0) sh[threadIdx.x >> 5] = s;
    __syncthreads();

    if (threadIdx.x < 32) {
        float v = (threadIdx.x < 8) ? sh[threadIdx.x] : 0.0f;
        #pragma unroll
        for (int o = 4; o > 0; o >>= 1)
            v += __shfl_down_sync(0xffffffffu, v, o);
        if (threadIdx.x == 0) {
            out[0] = v;
            g_gen = gen;   // next replay expects gen+1 (kernel-boundary visibility)
        }
    }
}

extern "C" void kernel_launch(void* const* d_in, const int* in_sizes, int n_in,
                              void* d_out, int out_size)
{
    const float* x      = (const float*)d_in[0];
    const int*   target = (const int*)d_in[1];
    float*       out    = (float*)d_out;

    const int N = in_sizes[1];         // 4096 rows
    const int V = in_sizes[0] / N;     // 32000 vocab

    ls_kernel<<<N + 1, 256>>>(x, target, out, V, N);
}

// round 17
// speedup vs baseline: 1.0222x; 1.0222x over previous
#include <cuda_runtime.h>
#include <cuda_bf16.h>

#define PADDING_IDX 0
#define SMOOTHING   0.1f
#define MAX_ROWS    8192

// Generation-tagged partial slots: {f32 value, u32 gen} in one aligned 8B word.
// One 8B store publishes value+tag atomically -> no fences/atomics anywhere.
// __device__ globals: allocation-free per harness rules.
__device__ unsigned long long g_slot[MAX_ROWS];   // zero-init: gen=0
__device__ unsigned int       g_gen = 0;          // bumped by spinner each launch

__device__ __forceinline__ void slot_store(int r, float v, unsigned int gen) {
    unsigned long long w =
        ((unsigned long long)gen << 32) | (unsigned long long)__float_as_uint(v);
    asm volatile("st.global.volatile.u64 [%0], %1;"
                 :: "l"(&g_slot[r]), "l"(w) : "memory");
}
__device__ __forceinline__ unsigned long long slot_load(int r) {
    unsigned long long w;
    asm volatile("ld.global.volatile.u64 %0, [%1];"
                 : "=l"(w) : "l"(&g_slot[r]) : "memory");
    return w;
}

// CONFIRMED OPTIMUM (R10/R15: 79.90/80.19us, ~6.6TB/s = LTS chip cap).
// grid = N+1. blockIdx 1..N: one row each — simple single-accumulator float4
// stream (32 regs -> 8 blocks/SM; measured binding constraint), default cache
// policy (evict-first measured -2.5%), gather in epilogue (hidden by 8-block
// overlap). blockIdx 0: hot consume-as-ready sweep spinner — consumes
// partials as they arrive; tail after last worker ~ 1 sweep.
// Fixed per-thread slot order -> bitwise-deterministic result.
// NOTE: target is int32 on device (JAX x64-disabled downcasts int64 -> int32).
__global__ void __launch_bounds__(256)
ls_kernel(const float* __restrict__ x,
          const int* __restrict__ target,
          float* __restrict__ out,
          int V, int N)
{
    __shared__ float sh[8];
    const unsigned int gen = g_gen + 1u;   // L2-hot broadcast; stable during launch

    if (blockIdx.x != 0) {
        // ---------------- worker: stream one row ----------------
        const int r = blockIdx.x - 1;
        const int t = target[r];

        if (t == PADDING_IDX || t < 0 || t >= V) {
            if (threadIdx.x == 0) slot_store(r, 0.0f, gen);
            return;
        }

        const size_t row_off = (size_t)r * (size_t)V;
        const float4* __restrict__ row4 = reinterpret_cast<const float4*>(x + row_off);
        const int nv4 = V >> 2;                      // 32000 -> 8000 float4

        float s = 0.0f;
        for (int i = threadIdx.x; i < nv4; i += blockDim.x) {
            float4 v = row4[i];
            s += (v.x + v.y) + (v.z + v.w);
        }
        for (int i = (nv4 << 2) + threadIdx.x; i < V; i += blockDim.x)
            s += x[row_off + i];                     // tail (unused for V=32000)

        #pragma unroll
        for (int o = 16; o > 0; o >>= 1)
            s += __shfl_down_sync(0xffffffffu, s, o);
        if ((threadIdx.x & 31) == 0) sh[threadIdx.x >> 5] = s;
        __syncthreads();

        if (threadIdx.x < 32) {
            float v = (threadIdx.x < 8) ? sh[threadIdx.x] : 0.0f;
            #pragma unroll
            for (int o = 4; o > 0; o >>= 1)
                v += __shfl_down_sync(0xffffffffu, v, o);
            if (threadIdx.x == 0) {
                const float g = x[row_off + (size_t)t];   // gather, L2-hot
                slot_store(r, -(SMOOTHING / (float)V) * v - (1.0f - SMOOTHING) * g, gen);
            }
        }
        return;
    }

    // ------------- spinner (block 0): consume-as-ready sweep -------------
    // Thread t owns slots {t, t+256, ..., t+3840}. Accumulation is in fixed
    // slot order per thread via ordered bit-scan of `pend` -> deterministic.
    const int nslots = (N + 255) >> 8;               // 16 for N=4096
    float acc[16];
    #pragma unroll
    for (int k = 0; k < 16; k++) acc[k] = 0.0f;

    unsigned int pend = (nslots >= 32) ? 0xFFFFFFFFu : ((1u << nslots) - 1u);
    #pragma unroll
    for (int k = 0; k < 16; k++)
        if ((int)threadIdx.x + (k << 8) >= N) pend &= ~(1u << k);

    while (pend) {
        unsigned int made = 0;
        #pragma unroll
        for (int k = 0; k < 16; k++) {
            if (pend & (1u << k)) {
                // independent volatile loads across k -> pipelined (MLP)
                unsigned long long w = slot_load(threadIdx.x + (k << 8));
                if ((unsigned int)(w >> 32) == gen) {
                    acc[k] = __uint_as_float((unsigned int)w);
                    pend &= ~(1u << k);
                    made = 1;
                }
            }
        }
        if (!made) __nanosleep(128);                 // back off only if stalled
    }

    float s = 0.0f;
    #pragma unroll
    for (int k = 0; k < 16; k++) s += acc[k];

    #pragma unroll
    for (int o = 16; o > 0; o >>= 1)
        s += __shfl_down_sync(0xffffffffu, s, o);
    if ((threadIdx.x & 31) == 0) sh[threadIdx.x >> 5] = s;
    __syncthreads();

    if (threadIdx.x < 32) {
        float v = (threadIdx.x < 8) ? sh[threadIdx.x] : 0.0f;
        #pragma unroll
        for (int o = 4; o > 0; o >>= 1)
            v += __shfl_down_sync(0xffffffffu, v, o);
        if (threadIdx.x == 0) {
            out[0] = v;
            g_gen = gen;   // next replay expects gen+1 (kernel-boundary visibility)
        }
    }
}

extern "C" void kernel_launch(void* const* d_in, const int* in_sizes, int n_in,
                              void* d_out, int out_size)
{
    const float* x      = (const float*)d_in[0];
    const int*   target = (const int*)d_in[1];
    float*       out    = (float*)d_out;

    const int N = in_sizes[1];         // 4096 rows
    const int V = in_sizes[0] / N;     // 32000 vocab

    ls_kernel<<<N + 1, 256>>>(x, target, out, V, N);
}